// round 1
// baseline (speedup 1.0000x reference)
#include <cuda_runtime.h>

#define NSAMPLE 32
#define RADIUS2 1.0f
#define MAXN    8192

// Scratch (no device allocation allowed — __device__ globals)
__device__ int g_ball_idx[MAXN * NSAMPLE];
__device__ int g_count[MAXN];
__device__ int g_offset[MAXN];

// ---------------------------------------------------------------------------
// Phase 0: zero the output (harness poisons it with 0xAA; reference pads zeros)
// ---------------------------------------------------------------------------
__global__ void zero_kernel(float* __restrict__ out, long n) {
    long i = ((long)blockIdx.x * blockDim.x + threadIdx.x) * 4;
    if (i + 3 < n) {
        *reinterpret_cast<float4*>(out + i) = make_float4(0.f, 0.f, 0.f, 0.f);
    } else {
        for (; i < n; i++) out[i] = 0.f;
    }
}

// ---------------------------------------------------------------------------
// Phase 1: per-point query. One warp per xyz point.
//   Coarse: ballot over rois (point inside roi bounding sphere).
//   Fine:   for each passing roi (ascending m), warp-sweep K grid points,
//           record first <=32 matches in (m*K + k) order via ballot ranks.
// ---------------------------------------------------------------------------
__global__ void phase1_kernel(const float* __restrict__ xyz,
                              const float* __restrict__ new_xyz,
                              const float* __restrict__ rois,
                              int Nb, int M, int K, int N) {
    int gw   = (blockIdx.x * blockDim.x + threadIdx.x) >> 5;
    int lane = threadIdx.x & 31;
    if (gw >= N) return;
    const int p = gw;
    const int b = p / Nb;
    const float px = xyz[3 * p + 0];
    const float py = xyz[3 * p + 1];
    const float pz = xyz[3 * p + 2];

    int count = 0;
    const int base_flat = b * M * K;

    for (int mr = 0; mr < M && count < NSAMPLE; mr += 32) {
        int m_l = mr + lane;
        bool inb = false;
        if (m_l < M) {
            const float* ro = rois + (size_t)(b * M + m_l) * 7;
            float dx = px - ro[0], dy = py - ro[1], dz = pz - ro[2];
            float da = ro[3], db = ro[4], dc = ro[5];
            float r2 = da * da + db * db + dc * dc;
            inb = (dx * dx + dy * dy + dz * dz) <= r2;
        }
        unsigned bm = __ballot_sync(0xffffffffu, inb);
        while (bm && count < NSAMPLE) {
            int m = mr + __ffs(bm) - 1;
            bm &= bm - 1;
            const float* gp = new_xyz + (size_t)(base_flat + m * K) * 3;
            for (int kb = 0; kb < K && count < NSAMPLE; kb += 32) {
                int k = kb + lane;
                bool hit = false;
                if (k < K) {
                    float dx = px - gp[3 * k + 0];
                    float dy = py - gp[3 * k + 1];
                    float dz = pz - gp[3 * k + 2];
                    hit = (dx * dx + dy * dy + dz * dz) <= RADIUS2;
                }
                unsigned hm = __ballot_sync(0xffffffffu, hit);
                if (hit) {
                    int rank = count + __popc(hm & ((1u << lane) - 1u));
                    if (rank < NSAMPLE)
                        g_ball_idx[p * NSAMPLE + rank] = base_flat + m * K + k;
                }
                count += __popc(hm);
            }
        }
    }
    if (lane == 0) g_count[p] = count < NSAMPLE ? count : NSAMPLE;
}

// ---------------------------------------------------------------------------
// Phase 2: exclusive scan of per-point counts (single block, N <= 8192)
// ---------------------------------------------------------------------------
__global__ void scan_kernel(int N) {
    __shared__ int wsum[32];
    const int T = blockDim.x;           // 1024
    int tid  = threadIdx.x;
    int per  = (N + T - 1) / T;         // <= 8
    int loc[8];
    int sum = 0;
    int base = tid * per;
    for (int i = 0; i < per; i++) {
        int idx = base + i;
        int v = (idx < N) ? g_count[idx] : 0;
        loc[i] = sum;
        sum += v;
    }
    int lane = tid & 31, wid = tid >> 5;
    int x = sum;
    #pragma unroll
    for (int off = 1; off < 32; off <<= 1) {
        int y = __shfl_up_sync(0xffffffffu, x, off);
        if (lane >= off) x += y;
    }
    if (lane == 31) wsum[wid] = x;
    __syncthreads();
    if (wid == 0) {
        int w = wsum[lane];
        #pragma unroll
        for (int off = 1; off < 32; off <<= 1) {
            int y = __shfl_up_sync(0xffffffffu, w, off);
            if (lane >= off) w += y;
        }
        wsum[lane] = w;
    }
    __syncthreads();
    int excl = x - sum + (wid > 0 ? wsum[wid - 1] : 0);
    for (int i = 0; i < per; i++) {
        int idx = base + i;
        if (idx < N) g_offset[idx] = excl + loc[i];
    }
}

// ---------------------------------------------------------------------------
// Phase 3: gather + write. One warp per (point, sample) slot.
//   out row (35 floats): [xyz[p]-new_xyz[g] (3), features[p] (C)]
//   plus set_new_indices as float at idx_base + dst (if present in out).
// ---------------------------------------------------------------------------
__global__ void write_kernel(const float* __restrict__ xyz,
                             const float* __restrict__ new_xyz,
                             const float* __restrict__ features,
                             float* __restrict__ out,
                             int N, int C, int write_idx, long idx_base) {
    int gw   = (blockIdx.x * blockDim.x + threadIdx.x) >> 5;
    int lane = threadIdx.x & 31;
    int p = gw >> 5;      // gw / NSAMPLE
    int s = gw & 31;      // gw % NSAMPLE
    if (p >= N) return;
    if (s >= g_count[p]) return;

    int dst = g_offset[p] + s;
    int g   = g_ball_idx[p * NSAMPLE + s];
    int CC  = 3 + C;      // 35
    float* o = out + (size_t)dst * CC;

    float v = 0.f;
    if (lane < 3)        v = xyz[3 * p + lane] - new_xyz[3 * (size_t)g + lane];
    else if (lane < CC)  v = features[(size_t)p * C + (lane - 3)];
    if (lane < CC)       o[lane] = v;

    int lane2 = lane + 32;
    if (lane2 < CC)      o[lane2] = features[(size_t)p * C + (lane2 - 3)];

    if (write_idx && lane == 0) out[idx_base + dst] = (float)g;
}

// ---------------------------------------------------------------------------
extern "C" void kernel_launch(void* const* d_in, const int* in_sizes, int n_in,
                              void* d_out, int out_size) {
    const float* xyz      = (const float*)d_in[0];
    // d_in[1] = xyz_batch_cnt (int32) — only its length (B) matters
    const float* new_xyz  = (const float*)d_in[2];
    const float* rois     = (const float*)d_in[3];
    const float* features = (const float*)d_in[4];

    const int B  = in_sizes[1];
    const int N  = in_sizes[0] / 3;
    const int Nb = N / B;
    const int M  = in_sizes[3] / (B * 7);
    const int K  = in_sizes[2] / (B * M * 3);
    const int C  = in_sizes[4] / N;
    const long L = (long)N * NSAMPLE;
    const int CC = 3 + C;

    float* out = (float*)d_out;

    // Phase 0: zero whole output
    {
        long n = (long)out_size;
        long n4 = (n + 3) / 4;
        int tpb = 256;
        int blocks = (int)((n4 + tpb - 1) / tpb);
        zero_kernel<<<blocks, tpb>>>(out, n);
    }
    // Phase 1: query (warp per point)
    {
        long threads = (long)N * 32;
        phase1_kernel<<<(int)((threads + 255) / 256), 256>>>(xyz, new_xyz, rois,
                                                             Nb, M, K, N);
    }
    // Phase 2: scan counts
    scan_kernel<<<1, 1024>>>(N);
    // Phase 3: gather/write (warp per (p,s))
    {
        long threads = L * 32;
        int write_idx = ((long)out_size >= L * CC + L) ? 1 : 0;
        write_kernel<<<(int)((threads + 255) / 256), 256>>>(xyz, new_xyz, features,
                                                            out, N, C, write_idx,
                                                            L * (long)CC);
    }
}

// round 2
// speedup vs baseline: 1.0738x; 1.0738x over previous
#include <cuda_runtime.h>

#define NSAMPLE 32
#define RADIUS2 1.0f
#define MAXN    8192

__device__ int g_ball_idx[MAXN * NSAMPLE];
__device__ int g_count[MAXN];
__device__ int g_offset[MAXN];
__device__ int g_done;   // zero-initialized; self-resets each run

// ---------------------------------------------------------------------------
// Kernel A: [blocks 0..ZB) zero the output; [ZB..ZB+PB) do phase1 query;
// the last phase1 block to finish performs the exclusive scan of counts.
// ---------------------------------------------------------------------------
__global__ void fused_kernel(const float* __restrict__ xyz,
                             const float* __restrict__ new_xyz,
                             const float* __restrict__ rois,
                             float* __restrict__ out, long zn,
                             int ZB, int PB,
                             int Nb, int M, int K, int N) {
    if ((int)blockIdx.x < ZB) {
        // ---- zero-fill (grid-stride float4) ----
        long n4 = zn >> 2;
        long stride = (long)ZB * blockDim.x;
        for (long i = (long)blockIdx.x * blockDim.x + threadIdx.x; i < n4; i += stride)
            reinterpret_cast<float4*>(out)[i] = make_float4(0.f, 0.f, 0.f, 0.f);
        if (blockIdx.x == 0 && threadIdx.x < (zn & 3))
            out[(n4 << 2) + threadIdx.x] = 0.f;
        return;
    }

    // ---- phase 1: warp-per-point ball query ----
    int pb   = blockIdx.x - ZB;
    int lane = threadIdx.x & 31;
    int wid  = threadIdx.x >> 5;
    int p    = pb * (blockDim.x >> 5) + wid;

    if (p < N) {
        const int b = p / Nb;
        const float px = xyz[3 * p + 0];
        const float py = xyz[3 * p + 1];
        const float pz = xyz[3 * p + 2];
        int count = 0;
        const int base_flat = b * M * K;

        for (int mr = 0; mr < M && count < NSAMPLE; mr += 32) {
            int m_l = mr + lane;
            bool inb = false;
            if (m_l < M) {
                const float* ro = rois + (size_t)(b * M + m_l) * 7;
                float dx = px - ro[0], dy = py - ro[1], dz = pz - ro[2];
                float da = ro[3], db = ro[4], dc = ro[5];
                inb = (dx * dx + dy * dy + dz * dz) <= (da * da + db * db + dc * dc);
            }
            unsigned bm = __ballot_sync(0xffffffffu, inb);
            while (bm && count < NSAMPLE) {
                int m = mr + __ffs(bm) - 1;
                bm &= bm - 1;
                const float* gp = new_xyz + (size_t)(base_flat + m * K) * 3;
                for (int kb = 0; kb < K && count < NSAMPLE; kb += 32) {
                    int k = kb + lane;
                    bool hit = false;
                    if (k < K) {
                        float dx = px - gp[3 * k + 0];
                        float dy = py - gp[3 * k + 1];
                        float dz = pz - gp[3 * k + 2];
                        hit = (dx * dx + dy * dy + dz * dz) <= RADIUS2;
                    }
                    unsigned hm = __ballot_sync(0xffffffffu, hit);
                    if (hit) {
                        int rank = count + __popc(hm & ((1u << lane) - 1u));
                        if (rank < NSAMPLE)
                            g_ball_idx[p * NSAMPLE + rank] = base_flat + m * K + k;
                    }
                    count += __popc(hm);
                }
            }
        }
        if (lane == 0) g_count[p] = count < NSAMPLE ? count : NSAMPLE;
    }

    // ---- last phase1 block does the scan ----
    __shared__ int s_last;
    __shared__ int s_wsum[8];
    __syncthreads();
    if (threadIdx.x == 0) {
        __threadfence();
        s_last = (atomicAdd(&g_done, 1) == PB - 1) ? 1 : 0;
    }
    __syncthreads();
    if (!s_last) return;

    // single-block exclusive scan of g_count[0..N) with 256 threads
    {
        const int T   = blockDim.x;         // 256
        int tid  = threadIdx.x;
        int per  = (N + T - 1) / T;         // <= 32 for N<=8192
        int base = tid * per;
        int loc[32];
        int sum = 0;
        for (int i = 0; i < per; i++) {
            int idx = base + i;
            int v = (idx < N) ? g_count[idx] : 0;
            loc[i] = sum;
            sum += v;
        }
        int lane2 = tid & 31, w = tid >> 5;
        int x = sum;
        #pragma unroll
        for (int off = 1; off < 32; off <<= 1) {
            int y = __shfl_up_sync(0xffffffffu, x, off);
            if (lane2 >= off) x += y;
        }
        if (lane2 == 31) s_wsum[w] = x;
        __syncthreads();
        if (w == 0 && lane2 < 8) {
            int v = s_wsum[lane2];
            #pragma unroll
            for (int off = 1; off < 8; off <<= 1) {
                int y = __shfl_up_sync(0xffu, v, off);
                if (lane2 >= off) v += y;
            }
            s_wsum[lane2] = v;
        }
        __syncthreads();
        int excl = x - sum + (w > 0 ? s_wsum[w - 1] : 0);
        for (int i = 0; i < per; i++) {
            int idx = base + i;
            if (idx < N) g_offset[idx] = excl + loc[i];
        }
        if (threadIdx.x == 0) g_done = 0;   // reset for next graph replay
    }
}

// ---------------------------------------------------------------------------
// Kernel B: warp-per-point gather + write.
//   Preload features row (1/lane) and all sample indices + gathered new_xyz
//   (lane = sample, MLP=32), then stream `count` contiguous 35-float rows.
// ---------------------------------------------------------------------------
__global__ void write_kernel(const float* __restrict__ xyz,
                             const float* __restrict__ new_xyz,
                             const float* __restrict__ features,
                             float* __restrict__ out,
                             int N, int C, int write_idx, long idx_base) {
    int gw   = (blockIdx.x * blockDim.x + threadIdx.x) >> 5;
    int lane = threadIdx.x & 31;
    if (gw >= N) return;
    const int p = gw;

    int count = g_count[p];
    if (count == 0) return;
    int off = g_offset[p];

    // features row: lane holds features[p*C + lane]  (C == 32)
    float f = features[(size_t)p * C + lane];

    // per-lane sample data
    int   gs = 0;
    float nx = 0.f, ny = 0.f, nz = 0.f;
    if (lane < count) {
        gs = g_ball_idx[p * NSAMPLE + lane];
        const float* np_ = new_xyz + 3 * (size_t)gs;
        nx = np_[0]; ny = np_[1]; nz = np_[2];
    }

    float px = xyz[3 * p + 0];
    float py = xyz[3 * p + 1];
    float pz = xyz[3 * p + 2];

    const int CC = 3 + C;   // 35
    float* orow = out + (size_t)off * CC;

    float fshift = __shfl_sync(0xffffffffu, f, (lane - 3) & 31); // features[lane-3] for lane>=3
    float ftail  = __shfl_sync(0xffffffffu, f, (29 + lane) & 31); // features[29+lane] for lane<3

    for (int s = 0; s < count; s++) {
        float sx = __shfl_sync(0xffffffffu, nx, s);
        float sy = __shfl_sync(0xffffffffu, ny, s);
        float sz = __shfl_sync(0xffffffffu, nz, s);
        float v;
        if (lane == 0)      v = px - sx;
        else if (lane == 1) v = py - sy;
        else if (lane == 2) v = pz - sz;
        else                v = fshift;
        orow[lane] = v;
        if (lane < 3) orow[32 + lane] = ftail;
        orow += CC;
    }

    if (write_idx && lane < count)
        out[idx_base + off + lane] = (float)gs;
}

// ---------------------------------------------------------------------------
extern "C" void kernel_launch(void* const* d_in, const int* in_sizes, int n_in,
                              void* d_out, int out_size) {
    const float* xyz      = (const float*)d_in[0];
    const float* new_xyz  = (const float*)d_in[2];
    const float* rois     = (const float*)d_in[3];
    const float* features = (const float*)d_in[4];

    const int B  = in_sizes[1];
    const int N  = in_sizes[0] / 3;
    const int Nb = N / B;
    const int M  = in_sizes[3] / (B * 7);
    const int K  = in_sizes[2] / (B * M * 3);
    const int C  = in_sizes[4] / N;
    const long L = (long)N * NSAMPLE;
    const int CC = 3 + C;

    float* out = (float*)d_out;

    const int TPB = 256;
    const int ZB  = 256;                          // zero-fill blocks (grid-stride)
    const int PB  = (N + (TPB >> 5) - 1) / (TPB >> 5);   // phase1 blocks (warp/point)

    fused_kernel<<<ZB + PB, TPB>>>(xyz, new_xyz, rois, out, (long)out_size,
                                   ZB, PB, Nb, M, K, N);

    int write_idx = ((long)out_size >= L * CC + L) ? 1 : 0;
    long wthreads = (long)N * 32;
    write_kernel<<<(int)((wthreads + TPB - 1) / TPB), TPB>>>(xyz, new_xyz, features,
                                                             out, N, C, write_idx,
                                                             L * (long)CC);
}